// round 5
// baseline (speedup 1.0000x reference)
#include <cuda_runtime.h>
#include <cuda_bf16.h>

// ---------------------------------------------------------------------------
// GCN: out = log_softmax( A_hat( relu(A_hat(x W1) + b1) W2 ) + b2 )
// A_hat applied per edge: norm = dinv[src]*dinv[dst], aggregated to dst.
// This version builds a dst-CSR (count/scan/fill) so both aggregations are
// pure gathers (no float atomics), and fuses bias+log_softmax into gather2.
// edge_index is int32 on device (JAX x64 disabled).
// ---------------------------------------------------------------------------

#define N_CAP   50048
#define E_CAP   860160
#define F_IN    128
#define F_HID   128
#define F_OUT   16

__device__ int   g_cnt [N_CAP];            // in-degree (with self loops)
__device__ int   g_off [N_CAP];            // CSR row offsets (by dst)
__device__ int   g_cur [N_CAP];            // fill cursors
__device__ int   g_esrc[E_CAP];            // CSR: src node per slot
__device__ float g_dinv[N_CAP];
__device__ float g_h1  [N_CAP * F_HID];    // x @ W1
__device__ float g_agg1[N_CAP * F_HID];    // A_hat h1
__device__ float g_h2  [N_CAP * F_OUT];    // relu(agg1+b1) @ W2

// ---------------------------------------------------------------------------
// 0) zero degree counters
// ---------------------------------------------------------------------------
__global__ void zero_cnt_kernel(int n) {
    int i = blockIdx.x * blockDim.x + threadIdx.x;
    if (i < n) g_cnt[i] = 0;
}

// ---------------------------------------------------------------------------
// 1) count: cnt[dst]++ per edge (int RED)
// ---------------------------------------------------------------------------
__global__ void count_kernel(const int* __restrict__ ei, int E) {
    int e = blockIdx.x * blockDim.x + threadIdx.x;
    if (e >= E) return;
    atomicAdd(&g_cnt[ei[E + e]], 1);
}

// ---------------------------------------------------------------------------
// 2) single-block exclusive scan over degrees -> offsets, cursors, dinv
// ---------------------------------------------------------------------------
__global__ __launch_bounds__(1024) void scan_kernel(int n) {
    __shared__ int part[1024];
    const int t  = threadIdx.x;
    const int CH = (n + 1023) / 1024;
    const int beg = t * CH;
    const int end = min(beg + CH, n);

    int s = 0;
    for (int i = beg; i < end; i++) s += g_cnt[i];
    part[t] = s;
    __syncthreads();

    // Hillis-Steele inclusive scan over 1024 partials
    for (int off = 1; off < 1024; off <<= 1) {
        int v = part[t];
        int u = (t >= off) ? part[t - off] : 0;
        __syncthreads();
        part[t] = v + u;
        __syncthreads();
    }

    int run = (t > 0) ? part[t - 1] : 0;   // exclusive prefix of this chunk
    for (int i = beg; i < end; i++) {
        int c = g_cnt[i];
        g_off[i] = run;
        g_cur[i] = run;
        g_dinv[i] = rsqrtf(fmaxf((float)c, 1.0f));
        run += c;
    }
}

// ---------------------------------------------------------------------------
// 3) fill CSR: slot = cur[dst]++; esrc[slot] = src
// ---------------------------------------------------------------------------
__global__ void fill_kernel(const int* __restrict__ ei, int E) {
    int e = blockIdx.x * blockDim.x + threadIdx.x;
    if (e >= E) return;
    int src = ei[e];
    int dst = ei[E + e];
    int pos = atomicAdd(&g_cur[dst], 1);
    g_esrc[pos] = src;
}

// ---------------------------------------------------------------------------
// 4) GEMM1: h1 = x @ W1  (fp32, 128x128 block tile, 8x8 micro-tile)
//    256 threads; thread (tx,ty): rows ty+16r, cols tx*8..+7
// ---------------------------------------------------------------------------
__global__ __launch_bounds__(256) void gemm1_kernel(
        const float* __restrict__ x, const float* __restrict__ W, int n) {
    __shared__ float Xs[128][33];     // padded: conflict-free column reads
    __shared__ float Ws[32][128];

    const int tid = threadIdx.x;
    const int tx  = tid & 15;
    const int ty  = tid >> 4;
    const int rowBase = blockIdx.x * 128;

    float acc[8][8];
    #pragma unroll
    for (int r = 0; r < 8; r++)
        #pragma unroll
        for (int j = 0; j < 8; j++) acc[r][j] = 0.f;

    for (int kb = 0; kb < F_IN; kb += 32) {
        // X tile 128x32: 1024 float4 / 256 threads = 4 each
        #pragma unroll
        for (int i = 0; i < 4; i++) {
            int f4 = tid + i * 256;
            int r  = f4 >> 3;           // 8 float4 per row
            int c  = (f4 & 7) << 2;
            int grow = rowBase + r;
            float4 v = (grow < n)
                ? *reinterpret_cast<const float4*>(x + (size_t)grow * F_IN + kb + c)
                : make_float4(0.f, 0.f, 0.f, 0.f);
            Xs[r][c]     = v.x;
            Xs[r][c + 1] = v.y;
            Xs[r][c + 2] = v.z;
            Xs[r][c + 3] = v.w;
        }
        // W tile 32x128: coalesced float4
        #pragma unroll
        for (int i = 0; i < 4; i++) {
            int f4 = tid + i * 256;
            int r  = f4 >> 5;
            int c  = (f4 & 31) << 2;
            *reinterpret_cast<float4*>(&Ws[r][c]) =
                *reinterpret_cast<const float4*>(W + (size_t)(kb + r) * F_HID + c);
        }
        __syncthreads();

        #pragma unroll
        for (int k = 0; k < 32; k++) {
            float b[8];
            *reinterpret_cast<float4*>(&b[0]) = *reinterpret_cast<float4*>(&Ws[k][tx * 8]);
            *reinterpret_cast<float4*>(&b[4]) = *reinterpret_cast<float4*>(&Ws[k][tx * 8 + 4]);
            float a[8];
            #pragma unroll
            for (int r = 0; r < 8; r++) a[r] = Xs[ty + r * 16][k];
            #pragma unroll
            for (int r = 0; r < 8; r++)
                #pragma unroll
                for (int j = 0; j < 8; j++) acc[r][j] += a[r] * b[j];
        }
        __syncthreads();
    }

    #pragma unroll
    for (int r = 0; r < 8; r++) {
        int grow = rowBase + ty + r * 16;
        if (grow < n) {
            float* op = g_h1 + (size_t)grow * F_HID + tx * 8;
            *reinterpret_cast<float4*>(op)     = make_float4(acc[r][0], acc[r][1], acc[r][2], acc[r][3]);
            *reinterpret_cast<float4*>(op + 4) = make_float4(acc[r][4], acc[r][5], acc[r][6], acc[r][7]);
        }
    }
}

// ---------------------------------------------------------------------------
// 5) gather1: agg1[d] = dinv[d] * sum_{e in CSR[d]} dinv[src] * h1[src]
//    warp per dst; 32-edge index batches via shuffle; float4 per lane
// ---------------------------------------------------------------------------
__global__ __launch_bounds__(256) void gather1_kernel(int n) {
    int w    = (blockIdx.x * blockDim.x + threadIdx.x) >> 5;
    int lane = threadIdx.x & 31;
    if (w >= n) return;                       // whole warps exit together

    const int off = g_off[w];
    const int cnt = g_cnt[w];

    float4 acc = make_float4(0.f, 0.f, 0.f, 0.f);
    for (int base = 0; base < cnt; base += 32) {
        int j = base + lane;
        int s = 0; float ds = 0.f;
        if (j < cnt) { s = g_esrc[off + j]; ds = g_dinv[s]; }
        int m = min(32, cnt - base);
        for (int jj = 0; jj < m; jj++) {
            int   sj = __shfl_sync(0xffffffffu, s,  jj);
            float nj = __shfl_sync(0xffffffffu, ds, jj);
            float4 v = reinterpret_cast<const float4*>(g_h1 + (size_t)sj * F_HID)[lane];
            acc.x += v.x * nj; acc.y += v.y * nj;
            acc.z += v.z * nj; acc.w += v.w * nj;
        }
    }
    float dd = g_dinv[w];
    acc.x *= dd; acc.y *= dd; acc.z *= dd; acc.w *= dd;
    reinterpret_cast<float4*>(g_agg1 + (size_t)w * F_HID)[lane] = acc;
}

// ---------------------------------------------------------------------------
// 6) GEMM2 fused: h2 = relu(agg1 + b1) @ W2
// ---------------------------------------------------------------------------
__global__ __launch_bounds__(256) void gemm2_kernel(
        const float* __restrict__ b1, const float* __restrict__ W2, int n) {
    __shared__ float Ws[F_HID * F_OUT];
    __shared__ float bs[F_HID];
    __shared__ float Hs[16][F_HID];

    const int tid = threadIdx.x;
    for (int i = tid; i < F_HID * F_OUT; i += 256) Ws[i] = W2[i];
    if (tid < F_HID) bs[tid] = b1[tid];

    int rowBase = blockIdx.x * 16;
    #pragma unroll
    for (int i = 0; i < 2; i++) {
        int f4 = tid + i * 256;
        int r  = f4 >> 5;
        int c  = (f4 & 31) << 2;
        int grow = rowBase + r;
        float4 v = (grow < n)
            ? *reinterpret_cast<const float4*>(g_agg1 + (size_t)grow * F_HID + c)
            : make_float4(0.f, 0.f, 0.f, 0.f);
        *reinterpret_cast<float4*>(&Hs[r][c]) = v;
    }
    __syncthreads();

    int j  = tid & 15;
    int rl = tid >> 4;
    int row = rowBase + rl;
    if (row >= n) return;

    float acc = 0.f;
    #pragma unroll
    for (int k = 0; k < F_HID; k++) {
        float h = fmaxf(Hs[rl][k] + bs[k], 0.f);
        acc += h * Ws[k * F_OUT + j];
    }
    g_h2[(size_t)row * F_OUT + j] = acc;
}

// ---------------------------------------------------------------------------
// 7) gather2 + b2 + log_softmax fused: 16 lanes per dst (2 dst per warp)
// ---------------------------------------------------------------------------
__global__ __launch_bounds__(256) void gather2_lsm_kernel(
        const float* __restrict__ b2, float* __restrict__ out, int n) {
    const int slot   = threadIdx.x >> 4;          // 0..15 dst slots per block
    const int lane16 = threadIdx.x & 15;
    int d = blockIdx.x * 16 + slot;
    bool valid = (d < n);
    int dc = valid ? d : 0;                       // clamp; lanes stay resident

    const int off = g_off[dc];
    const int cnt = valid ? g_cnt[dc] : 0;

    float acc = 0.f;
    for (int j = 0; j < cnt; j++) {
        int s = g_esrc[off + j];
        acc += g_dinv[s] * g_h2[(size_t)s * F_OUT + lane16];
    }
    acc = acc * g_dinv[dc] + b2[lane16];

    // 16-lane log_softmax via xor shuffles (width 16)
    float m = acc;
    #pragma unroll
    for (int mask = 8; mask >= 1; mask >>= 1)
        m = fmaxf(m, __shfl_xor_sync(0xffffffffu, m, mask, 16));
    float ex = expf(acc - m);
    float ss = ex;
    #pragma unroll
    for (int mask = 8; mask >= 1; mask >>= 1)
        ss += __shfl_xor_sync(0xffffffffu, ss, mask, 16);
    if (valid)
        out[(size_t)d * F_OUT + lane16] = acc - m - logf(ss);
}

// ---------------------------------------------------------------------------
// launch
// ---------------------------------------------------------------------------
extern "C" void kernel_launch(void* const* d_in, const int* in_sizes, int n_in,
                              void* d_out, int out_size) {
    const float* x  = (const float*)d_in[0];
    const int*   ei = (const int*)d_in[1];      // int32
    const float* W1 = (const float*)d_in[2];
    const float* b1 = (const float*)d_in[3];
    const float* W2 = (const float*)d_in[4];
    const float* b2 = (const float*)d_in[5];
    float* out = (float*)d_out;

    const int n = in_sizes[0] / F_IN;       // 50000
    const int E = in_sizes[1] / 2;          // 850000

    zero_cnt_kernel<<<(n + 255) / 256, 256>>>(n);
    count_kernel<<<(E + 255) / 256, 256>>>(ei, E);
    scan_kernel<<<1, 1024>>>(n);
    fill_kernel<<<(E + 255) / 256, 256>>>(ei, E);
    gemm1_kernel<<<(n + 127) / 128, 256>>>(x, W1, n);
    gather1_kernel<<<(n + 7) / 8, 256>>>(n);                 // warp per dst
    gemm2_kernel<<<(n + 15) / 16, 256>>>(b1, W2, n);
    gather2_lsm_kernel<<<(n + 15) / 16, 256>>>(b2, out, n);
}

// round 7
// speedup vs baseline: 1.6134x; 1.6134x over previous
#include <cuda_runtime.h>
#include <cuda_bf16.h>

// ---------------------------------------------------------------------------
// GCN: out = log_softmax( A_hat( relu(A_hat(x W1) + b1) W2 ) + b2 )
// dst-CSR build (count / parallel-scan / fill) -> both aggregations are pure
// gathers (no float atomics); bias+log_softmax fused into gather2.
// edge_index is int32 on device (JAX x64 disabled).
// ---------------------------------------------------------------------------

#define N_CAP   50048
#define E_CAP   860160
#define F_IN    128
#define F_HID   128
#define F_OUT   16
#define NB_CAP  1024     // supports n <= 262144

__device__ int   g_cnt [N_CAP];            // in-degree (with self loops)
__device__ int   g_off [N_CAP];            // CSR row offsets (by dst)
__device__ int   g_cur [N_CAP];            // fill cursors
__device__ int   g_bsum[NB_CAP];           // per-block sums
__device__ int   g_bpre[NB_CAP];           // exclusive prefix of block sums
__device__ int   g_esrc[E_CAP];            // CSR: src node per slot
__device__ float g_dinv[N_CAP];
__device__ float g_h1  [N_CAP * F_HID];    // x @ W1
__device__ float g_agg1[N_CAP * F_HID];    // A_hat h1
__device__ float g_h2  [N_CAP * F_OUT];    // relu(agg1+b1) @ W2

// ---------------------------------------------------------------------------
// 0) zero degree counters
// ---------------------------------------------------------------------------
__global__ void zero_cnt_kernel(int n) {
    int i = blockIdx.x * blockDim.x + threadIdx.x;
    if (i < n) g_cnt[i] = 0;
}

// ---------------------------------------------------------------------------
// 1) count: cnt[dst]++ per edge (int RED)
// ---------------------------------------------------------------------------
__global__ void count_kernel(const int* __restrict__ ei, int E) {
    int e = blockIdx.x * blockDim.x + threadIdx.x;
    if (e >= E) return;
    atomicAdd(&g_cnt[ei[E + e]], 1);
}

// ---------------------------------------------------------------------------
// 2a) per-block reduce: bsum[b] = sum of cnt[b*256 .. b*256+255]
// ---------------------------------------------------------------------------
__global__ __launch_bounds__(256) void scanA_kernel(int n) {
    __shared__ int ws[8];
    int i = blockIdx.x * 256 + threadIdx.x;
    int v = (i < n) ? g_cnt[i] : 0;
    int lane = threadIdx.x & 31, wid = threadIdx.x >> 5;
    int s = v;
    #pragma unroll
    for (int o = 16; o >= 1; o >>= 1) s += __shfl_xor_sync(0xffffffffu, s, o);
    if (lane == 0) ws[wid] = s;
    __syncthreads();
    if (threadIdx.x == 0) {
        int t = 0;
        #pragma unroll
        for (int w = 0; w < 8; w++) t += ws[w];
        g_bsum[blockIdx.x] = t;
    }
}

// ---------------------------------------------------------------------------
// 2b) one block: exclusive scan of NB block sums (NB <= 1024)
// ---------------------------------------------------------------------------
__global__ __launch_bounds__(1024) void scanB_kernel(int nb) {
    __shared__ int part[NB_CAP];
    int t = threadIdx.x;
    int v = (t < nb) ? g_bsum[t] : 0;
    part[t] = v;
    __syncthreads();
    for (int o = 1; o < NB_CAP; o <<= 1) {
        int u = (t >= o) ? part[t - o] : 0;
        __syncthreads();
        part[t] += u;
        __syncthreads();
    }
    if (t < nb) g_bpre[t] = part[t] - v;   // exclusive
}

// ---------------------------------------------------------------------------
// 2c) per-block exclusive scan + block prefix -> off, cur, dinv  (coalesced)
// ---------------------------------------------------------------------------
__global__ __launch_bounds__(256) void scanC_kernel(int n) {
    __shared__ int wsum[8];
    int i = blockIdx.x * 256 + threadIdx.x;
    int v = (i < n) ? g_cnt[i] : 0;
    int lane = threadIdx.x & 31, wid = threadIdx.x >> 5;

    // inclusive warp scan of v
    int x = v;
    #pragma unroll
    for (int o = 1; o < 32; o <<= 1) {
        int y = __shfl_up_sync(0xffffffffu, x, o);
        if (lane >= o) x += y;
    }
    if (lane == 31) wsum[wid] = x;         // warp totals
    __syncthreads();

    // thread 0: convert 8 warp totals to exclusive warp prefixes
    if (threadIdx.x == 0) {
        int run = 0;
        #pragma unroll
        for (int w = 0; w < 8; w++) { int t = wsum[w]; wsum[w] = run; run += t; }
    }
    __syncthreads();

    if (i < n) {
        int off = g_bpre[blockIdx.x] + wsum[wid] + (x - v);   // exclusive
        g_off[i] = off;
        g_cur[i] = off;
        g_dinv[i] = rsqrtf(fmaxf((float)v, 1.0f));
    }
}

// ---------------------------------------------------------------------------
// 3) fill CSR: slot = cur[dst]++; esrc[slot] = src
// ---------------------------------------------------------------------------
__global__ void fill_kernel(const int* __restrict__ ei, int E) {
    int e = blockIdx.x * blockDim.x + threadIdx.x;
    if (e >= E) return;
    int src = ei[e];
    int dst = ei[E + e];
    int pos = atomicAdd(&g_cur[dst], 1);
    g_esrc[pos] = src;
}

// ---------------------------------------------------------------------------
// 4) GEMM1: h1 = x @ W1  (fp32, 128x128 block tile, 8x8 micro-tile)
// ---------------------------------------------------------------------------
__global__ __launch_bounds__(256) void gemm1_kernel(
        const float* __restrict__ x, const float* __restrict__ W, int n) {
    __shared__ float Xs[128][33];
    __shared__ float Ws[32][128];

    const int tid = threadIdx.x;
    const int tx  = tid & 15;
    const int ty  = tid >> 4;
    const int rowBase = blockIdx.x * 128;

    float acc[8][8];
    #pragma unroll
    for (int r = 0; r < 8; r++)
        #pragma unroll
        for (int j = 0; j < 8; j++) acc[r][j] = 0.f;

    for (int kb = 0; kb < F_IN; kb += 32) {
        #pragma unroll
        for (int i = 0; i < 4; i++) {
            int f4 = tid + i * 256;
            int r  = f4 >> 3;
            int c  = (f4 & 7) << 2;
            int grow = rowBase + r;
            float4 v = (grow < n)
                ? *reinterpret_cast<const float4*>(x + (size_t)grow * F_IN + kb + c)
                : make_float4(0.f, 0.f, 0.f, 0.f);
            Xs[r][c]     = v.x;
            Xs[r][c + 1] = v.y;
            Xs[r][c + 2] = v.z;
            Xs[r][c + 3] = v.w;
        }
        #pragma unroll
        for (int i = 0; i < 4; i++) {
            int f4 = tid + i * 256;
            int r  = f4 >> 5;
            int c  = (f4 & 31) << 2;
            *reinterpret_cast<float4*>(&Ws[r][c]) =
                *reinterpret_cast<const float4*>(W + (size_t)(kb + r) * F_HID + c);
        }
        __syncthreads();

        #pragma unroll
        for (int k = 0; k < 32; k++) {
            float b[8];
            *reinterpret_cast<float4*>(&b[0]) = *reinterpret_cast<float4*>(&Ws[k][tx * 8]);
            *reinterpret_cast<float4*>(&b[4]) = *reinterpret_cast<float4*>(&Ws[k][tx * 8 + 4]);
            float a[8];
            #pragma unroll
            for (int r = 0; r < 8; r++) a[r] = Xs[ty + r * 16][k];
            #pragma unroll
            for (int r = 0; r < 8; r++)
                #pragma unroll
                for (int j = 0; j < 8; j++) acc[r][j] += a[r] * b[j];
        }
        __syncthreads();
    }

    #pragma unroll
    for (int r = 0; r < 8; r++) {
        int grow = rowBase + ty + r * 16;
        if (grow < n) {
            float* op = g_h1 + (size_t)grow * F_HID + tx * 8;
            *reinterpret_cast<float4*>(op)     = make_float4(acc[r][0], acc[r][1], acc[r][2], acc[r][3]);
            *reinterpret_cast<float4*>(op + 4) = make_float4(acc[r][4], acc[r][5], acc[r][6], acc[r][7]);
        }
    }
}

// ---------------------------------------------------------------------------
// 5) gather1: agg1[d] = dinv[d] * sum_{e in CSR[d]} dinv[src] * h1[src]
// ---------------------------------------------------------------------------
__global__ __launch_bounds__(256) void gather1_kernel(int n) {
    int w    = (blockIdx.x * blockDim.x + threadIdx.x) >> 5;
    int lane = threadIdx.x & 31;
    if (w >= n) return;

    const int off = g_off[w];
    const int cnt = g_cnt[w];

    float4 acc = make_float4(0.f, 0.f, 0.f, 0.f);
    for (int base = 0; base < cnt; base += 32) {
        int j = base + lane;
        int s = 0; float ds = 0.f;
        if (j < cnt) { s = g_esrc[off + j]; ds = g_dinv[s]; }
        int m = min(32, cnt - base);
        for (int jj = 0; jj < m; jj++) {
            int   sj = __shfl_sync(0xffffffffu, s,  jj);
            float nj = __shfl_sync(0xffffffffu, ds, jj);
            float4 v = reinterpret_cast<const float4*>(g_h1 + (size_t)sj * F_HID)[lane];
            acc.x += v.x * nj; acc.y += v.y * nj;
            acc.z += v.z * nj; acc.w += v.w * nj;
        }
    }
    float dd = g_dinv[w];
    acc.x *= dd; acc.y *= dd; acc.z *= dd; acc.w *= dd;
    reinterpret_cast<float4*>(g_agg1 + (size_t)w * F_HID)[lane] = acc;
}

// ---------------------------------------------------------------------------
// 6) GEMM2 fused: h2 = relu(agg1 + b1) @ W2
// ---------------------------------------------------------------------------
__global__ __launch_bounds__(256) void gemm2_kernel(
        const float* __restrict__ b1, const float* __restrict__ W2, int n) {
    __shared__ float Ws[F_HID * F_OUT];
    __shared__ float bs[F_HID];
    __shared__ float Hs[16][F_HID];

    const int tid = threadIdx.x;
    for (int i = tid; i < F_HID * F_OUT; i += 256) Ws[i] = W2[i];
    if (tid < F_HID) bs[tid] = b1[tid];

    int rowBase = blockIdx.x * 16;
    #pragma unroll
    for (int i = 0; i < 2; i++) {
        int f4 = tid + i * 256;
        int r  = f4 >> 5;
        int c  = (f4 & 31) << 2;
        int grow = rowBase + r;
        float4 v = (grow < n)
            ? *reinterpret_cast<const float4*>(g_agg1 + (size_t)grow * F_HID + c)
            : make_float4(0.f, 0.f, 0.f, 0.f);
        *reinterpret_cast<float4*>(&Hs[r][c]) = v;
    }
    __syncthreads();

    int j  = tid & 15;
    int rl = tid >> 4;
    int row = rowBase + rl;
    if (row >= n) return;

    float acc = 0.f;
    #pragma unroll
    for (int k = 0; k < F_HID; k++) {
        float h = fmaxf(Hs[rl][k] + bs[k], 0.f);
        acc += h * Ws[k * F_OUT + j];
    }
    g_h2[(size_t)row * F_OUT + j] = acc;
}

// ---------------------------------------------------------------------------
// 7) gather2 + b2 + log_softmax fused: 16 lanes per dst
// ---------------------------------------------------------------------------
__global__ __launch_bounds__(256) void gather2_lsm_kernel(
        const float* __restrict__ b2, float* __restrict__ out, int n) {
    const int slot   = threadIdx.x >> 4;
    const int lane16 = threadIdx.x & 15;
    int d = blockIdx.x * 16 + slot;
    bool valid = (d < n);
    int dc = valid ? d : 0;

    const int off = g_off[dc];
    const int cnt = valid ? g_cnt[dc] : 0;

    float acc = 0.f;
    for (int j = 0; j < cnt; j++) {
        int s = g_esrc[off + j];
        acc += g_dinv[s] * g_h2[(size_t)s * F_OUT + lane16];
    }
    acc = acc * g_dinv[dc] + b2[lane16];

    float m = acc;
    #pragma unroll
    for (int mask = 8; mask >= 1; mask >>= 1)
        m = fmaxf(m, __shfl_xor_sync(0xffffffffu, m, mask, 16));
    float ex = expf(acc - m);
    float ss = ex;
    #pragma unroll
    for (int mask = 8; mask >= 1; mask >>= 1)
        ss += __shfl_xor_sync(0xffffffffu, ss, mask, 16);
    if (valid)
        out[(size_t)d * F_OUT + lane16] = acc - m - logf(ss);
}

// ---------------------------------------------------------------------------
// launch
// ---------------------------------------------------------------------------
extern "C" void kernel_launch(void* const* d_in, const int* in_sizes, int n_in,
                              void* d_out, int out_size) {
    const float* x  = (const float*)d_in[0];
    const int*   ei = (const int*)d_in[1];      // int32
    const float* W1 = (const float*)d_in[2];
    const float* b1 = (const float*)d_in[3];
    const float* W2 = (const float*)d_in[4];
    const float* b2 = (const float*)d_in[5];
    float* out = (float*)d_out;

    const int n = in_sizes[0] / F_IN;       // 50000
    const int E = in_sizes[1] / 2;          // 850000
    const int nb = (n + 255) / 256;         // 196 blocks

    zero_cnt_kernel<<<(n + 255) / 256, 256>>>(n);
    count_kernel<<<(E + 255) / 256, 256>>>(ei, E);
    scanA_kernel<<<nb, 256>>>(n);
    scanB_kernel<<<1, 1024>>>(nb);
    scanC_kernel<<<nb, 256>>>(n);
    fill_kernel<<<(E + 255) / 256, 256>>>(ei, E);
    gemm1_kernel<<<(n + 127) / 128, 256>>>(x, W1, n);
    gather1_kernel<<<(n + 7) / 8, 256>>>(n);
    gemm2_kernel<<<(n + 15) / 16, 256>>>(b1, W2, n);
    gather2_lsm_kernel<<<(n + 15) / 16, 256>>>(b2, out, n);
}

// round 8
// speedup vs baseline: 1.7914x; 1.1103x over previous
#include <cuda_runtime.h>
#include <cuda_bf16.h>

// ---------------------------------------------------------------------------
// GCN: out = log_softmax( A_hat( relu(A_hat(x W1) + b1) W2 ) + b2 )
// dst-CSR build (count / parallel-scan / fill) -> aggregations are pure
// gathers. Layer-1 aggregation fused with GEMM2 (agg row never leaves SM).
// edge_index is int32 on device (JAX x64 disabled).
// ---------------------------------------------------------------------------

#define N_CAP   50048
#define E_CAP   860160
#define F_IN    128
#define F_HID   128
#define F_OUT   16
#define NB_CAP  256      // block-sum slots (n <= 65536)

__device__ int   g_cnt [N_CAP];            // in-degree (with self loops)
__device__ int   g_off [N_CAP];            // CSR row offsets (by dst)
__device__ int   g_cur [N_CAP];            // fill cursors
__device__ int   g_bsum[NB_CAP];           // per-block sums
__device__ int   g_bpre[NB_CAP];           // exclusive prefix of block sums
__device__ int   g_esrc[E_CAP];            // CSR: src node per slot
__device__ float g_dinv[N_CAP];
__device__ float g_h1  [N_CAP * F_HID];    // x @ W1
__device__ float g_h2  [N_CAP * F_OUT];    // relu(A_hat h1 + b1) @ W2

// ---------------------------------------------------------------------------
// 0) zero degree counters
// ---------------------------------------------------------------------------
__global__ void zero_cnt_kernel(int n) {
    int i = blockIdx.x * blockDim.x + threadIdx.x;
    if (i < n) g_cnt[i] = 0;
}

// ---------------------------------------------------------------------------
// 1) count: cnt[dst]++ per edge (int RED)
// ---------------------------------------------------------------------------
__global__ void count_kernel(const int* __restrict__ ei, int E) {
    int e = blockIdx.x * blockDim.x + threadIdx.x;
    if (e >= E) return;
    atomicAdd(&g_cnt[ei[E + e]], 1);
}

// ---------------------------------------------------------------------------
// 2a) per-block reduce: bsum[b] = sum of cnt[b*256 .. b*256+255]
// ---------------------------------------------------------------------------
__global__ __launch_bounds__(256) void scanA_kernel(int n) {
    __shared__ int ws[8];
    int i = blockIdx.x * 256 + threadIdx.x;
    int v = (i < n) ? g_cnt[i] : 0;
    int lane = threadIdx.x & 31, wid = threadIdx.x >> 5;
    int s = v;
    #pragma unroll
    for (int o = 16; o >= 1; o >>= 1) s += __shfl_xor_sync(0xffffffffu, s, o);
    if (lane == 0) ws[wid] = s;
    __syncthreads();
    if (threadIdx.x == 0) {
        int t = 0;
        #pragma unroll
        for (int w = 0; w < 8; w++) t += ws[w];
        g_bsum[blockIdx.x] = t;
    }
}

// ---------------------------------------------------------------------------
// 2b) one block (256 thr), warp-shuffle exclusive scan of nb block sums
// ---------------------------------------------------------------------------
__global__ __launch_bounds__(256) void scanB_kernel(int nb) {
    __shared__ int wsum[8];
    int t = threadIdx.x;
    int lane = t & 31, wid = t >> 5;
    int v = (t < nb) ? g_bsum[t] : 0;

    int x = v;
    #pragma unroll
    for (int o = 1; o < 32; o <<= 1) {
        int y = __shfl_up_sync(0xffffffffu, x, o);
        if (lane >= o) x += y;
    }
    if (lane == 31) wsum[wid] = x;
    __syncthreads();
    if (t == 0) {
        int run = 0;
        #pragma unroll
        for (int w = 0; w < 8; w++) { int s = wsum[w]; wsum[w] = run; run += s; }
    }
    __syncthreads();
    if (t < nb) g_bpre[t] = wsum[wid] + x - v;   // exclusive
}

// ---------------------------------------------------------------------------
// 2c) per-block exclusive scan + block prefix -> off, cur, dinv  (coalesced)
// ---------------------------------------------------------------------------
__global__ __launch_bounds__(256) void scanC_kernel(int n) {
    __shared__ int wsum[8];
    int i = blockIdx.x * 256 + threadIdx.x;
    int v = (i < n) ? g_cnt[i] : 0;
    int lane = threadIdx.x & 31, wid = threadIdx.x >> 5;

    int x = v;
    #pragma unroll
    for (int o = 1; o < 32; o <<= 1) {
        int y = __shfl_up_sync(0xffffffffu, x, o);
        if (lane >= o) x += y;
    }
    if (lane == 31) wsum[wid] = x;
    __syncthreads();
    if (threadIdx.x == 0) {
        int run = 0;
        #pragma unroll
        for (int w = 0; w < 8; w++) { int t = wsum[w]; wsum[w] = run; run += t; }
    }
    __syncthreads();

    if (i < n) {
        int off = g_bpre[blockIdx.x] + wsum[wid] + (x - v);   // exclusive
        g_off[i] = off;
        g_cur[i] = off;
        g_dinv[i] = rsqrtf(fmaxf((float)v, 1.0f));
    }
}

// ---------------------------------------------------------------------------
// 3) fill CSR: slot = cur[dst]++; esrc[slot] = src
// ---------------------------------------------------------------------------
__global__ void fill_kernel(const int* __restrict__ ei, int E) {
    int e = blockIdx.x * blockDim.x + threadIdx.x;
    if (e >= E) return;
    int src = ei[e];
    int dst = ei[E + e];
    int pos = atomicAdd(&g_cur[dst], 1);
    g_esrc[pos] = src;
}

// ---------------------------------------------------------------------------
// 4) GEMM1: h1 = x @ W1  (fp32, 128x128 block tile, 8x8 micro-tile)
// ---------------------------------------------------------------------------
__global__ __launch_bounds__(256) void gemm1_kernel(
        const float* __restrict__ x, const float* __restrict__ W, int n) {
    __shared__ float Xs[128][33];
    __shared__ float Ws[32][128];

    const int tid = threadIdx.x;
    const int tx  = tid & 15;
    const int ty  = tid >> 4;
    const int rowBase = blockIdx.x * 128;

    float acc[8][8];
    #pragma unroll
    for (int r = 0; r < 8; r++)
        #pragma unroll
        for (int j = 0; j < 8; j++) acc[r][j] = 0.f;

    for (int kb = 0; kb < F_IN; kb += 32) {
        #pragma unroll
        for (int i = 0; i < 4; i++) {
            int f4 = tid + i * 256;
            int r  = f4 >> 3;
            int c  = (f4 & 7) << 2;
            int grow = rowBase + r;
            float4 v = (grow < n)
                ? *reinterpret_cast<const float4*>(x + (size_t)grow * F_IN + kb + c)
                : make_float4(0.f, 0.f, 0.f, 0.f);
            Xs[r][c]     = v.x;
            Xs[r][c + 1] = v.y;
            Xs[r][c + 2] = v.z;
            Xs[r][c + 3] = v.w;
        }
        #pragma unroll
        for (int i = 0; i < 4; i++) {
            int f4 = tid + i * 256;
            int r  = f4 >> 5;
            int c  = (f4 & 31) << 2;
            *reinterpret_cast<float4*>(&Ws[r][c]) =
                *reinterpret_cast<const float4*>(W + (size_t)(kb + r) * F_HID + c);
        }
        __syncthreads();

        #pragma unroll
        for (int k = 0; k < 32; k++) {
            float b[8];
            *reinterpret_cast<float4*>(&b[0]) = *reinterpret_cast<float4*>(&Ws[k][tx * 8]);
            *reinterpret_cast<float4*>(&b[4]) = *reinterpret_cast<float4*>(&Ws[k][tx * 8 + 4]);
            float a[8];
            #pragma unroll
            for (int r = 0; r < 8; r++) a[r] = Xs[ty + r * 16][k];
            #pragma unroll
            for (int r = 0; r < 8; r++)
                #pragma unroll
                for (int j = 0; j < 8; j++) acc[r][j] += a[r] * b[j];
        }
        __syncthreads();
    }

    #pragma unroll
    for (int r = 0; r < 8; r++) {
        int grow = rowBase + ty + r * 16;
        if (grow < n) {
            float* op = g_h1 + (size_t)grow * F_HID + tx * 8;
            *reinterpret_cast<float4*>(op)     = make_float4(acc[r][0], acc[r][1], acc[r][2], acc[r][3]);
            *reinterpret_cast<float4*>(op + 4) = make_float4(acc[r][4], acc[r][5], acc[r][6], acc[r][7]);
        }
    }
}

// ---------------------------------------------------------------------------
// 5) FUSED gather1 + relu-bias + GEMM2:
//    per warp (dst d): row = dinv[d]*sum dinv[s]*h1[s]; h = relu(row + b1)
//    -> smem tile Hs[8][128]; block then computes h2[8 dst][16] = Hs @ W2.
// ---------------------------------------------------------------------------
__global__ __launch_bounds__(256) void layer1_fused_kernel(
        const float* __restrict__ b1, const float* __restrict__ W2, int n) {
    __shared__ float Ws[F_HID * F_OUT];   // 2048 floats
    __shared__ float bs[F_HID];
    __shared__ float Hs[8][F_HID];

    const int tid  = threadIdx.x;
    const int w    = tid >> 5;            // warp = dst slot (0..7)
    const int lane = tid & 31;

    for (int i = tid; i < F_HID * F_OUT; i += 256) Ws[i] = W2[i];
    if (tid < F_HID) bs[tid] = b1[tid];

    const int d = blockIdx.x * 8 + w;
    const bool valid = (d < n);
    const int off = valid ? g_off[d] : 0;
    const int cnt = valid ? g_cnt[d] : 0;

    float4 acc = make_float4(0.f, 0.f, 0.f, 0.f);
    for (int base = 0; base < cnt; base += 32) {
        int j = base + lane;
        int s = 0; float ds = 0.f;
        if (j < cnt) { s = g_esrc[off + j]; ds = g_dinv[s]; }
        int m = min(32, cnt - base);
        for (int jj = 0; jj < m; jj++) {
            int   sj = __shfl_sync(0xffffffffu, s,  jj);
            float nj = __shfl_sync(0xffffffffu, ds, jj);
            float4 v = reinterpret_cast<const float4*>(g_h1 + (size_t)sj * F_HID)[lane];
            acc.x += v.x * nj; acc.y += v.y * nj;
            acc.z += v.z * nj; acc.w += v.w * nj;
        }
    }

    __syncthreads();    // bs/Ws ready; all threads reach here (no early return)

    float dd = valid ? g_dinv[d] : 0.f;
    float4 h;
    h.x = fmaxf(acc.x * dd + bs[lane * 4 + 0], 0.f);
    h.y = fmaxf(acc.y * dd + bs[lane * 4 + 1], 0.f);
    h.z = fmaxf(acc.z * dd + bs[lane * 4 + 2], 0.f);
    h.w = fmaxf(acc.w * dd + bs[lane * 4 + 3], 0.f);
    *reinterpret_cast<float4*>(&Hs[w][lane * 4]) = h;
    __syncthreads();

    // mini-GEMM: 8 rows x 16 cols, 128 threads
    if (tid < 128) {
        int r = tid >> 4;
        int j = tid & 15;
        int dr = blockIdx.x * 8 + r;
        if (dr < n) {
            float s = 0.f;
            #pragma unroll
            for (int k = 0; k < F_HID; k++)
                s += Hs[r][k] * Ws[k * F_OUT + j];
            g_h2[(size_t)dr * F_OUT + j] = s;
        }
    }
}

// ---------------------------------------------------------------------------
// 6) gather2 + b2 + log_softmax fused: 16 lanes per dst
// ---------------------------------------------------------------------------
__global__ __launch_bounds__(256) void gather2_lsm_kernel(
        const float* __restrict__ b2, float* __restrict__ out, int n) {
    const int slot   = threadIdx.x >> 4;
    const int lane16 = threadIdx.x & 15;
    int d = blockIdx.x * 16 + slot;
    bool valid = (d < n);
    int dc = valid ? d : 0;

    const int off = g_off[dc];
    const int cnt = valid ? g_cnt[dc] : 0;

    float acc = 0.f;
    for (int j = 0; j < cnt; j++) {
        int s = g_esrc[off + j];
        acc += g_dinv[s] * g_h2[(size_t)s * F_OUT + lane16];
    }
    acc = acc * g_dinv[dc] + b2[lane16];

    float m = acc;
    #pragma unroll
    for (int mask = 8; mask >= 1; mask >>= 1)
        m = fmaxf(m, __shfl_xor_sync(0xffffffffu, m, mask, 16));
    float ex = expf(acc - m);
    float ss = ex;
    #pragma unroll
    for (int mask = 8; mask >= 1; mask >>= 1)
        ss += __shfl_xor_sync(0xffffffffu, ss, mask, 16);
    if (valid)
        out[(size_t)d * F_OUT + lane16] = acc - m - logf(ss);
}

// ---------------------------------------------------------------------------
// launch
// ---------------------------------------------------------------------------
extern "C" void kernel_launch(void* const* d_in, const int* in_sizes, int n_in,
                              void* d_out, int out_size) {
    const float* x  = (const float*)d_in[0];
    const int*   ei = (const int*)d_in[1];      // int32
    const float* W1 = (const float*)d_in[2];
    const float* b1 = (const float*)d_in[3];
    const float* W2 = (const float*)d_in[4];
    const float* b2 = (const float*)d_in[5];
    float* out = (float*)d_out;

    const int n = in_sizes[0] / F_IN;       // 50000
    const int E = in_sizes[1] / 2;          // 850000
    const int nb = (n + 255) / 256;         // 196 blocks

    zero_cnt_kernel<<<(n + 255) / 256, 256>>>(n);
    count_kernel<<<(E + 255) / 256, 256>>>(ei, E);
    scanA_kernel<<<nb, 256>>>(n);
    scanB_kernel<<<1, 256>>>(nb);
    scanC_kernel<<<nb, 256>>>(n);
    fill_kernel<<<(E + 255) / 256, 256>>>(ei, E);
    gemm1_kernel<<<(n + 127) / 128, 256>>>(x, W1, n);
    layer1_fused_kernel<<<(n + 7) / 8, 256>>>(b1, W2, n);
    gather2_lsm_kernel<<<(n + 15) / 16, 256>>>(b2, out, n);
}